// round 15
// baseline (speedup 1.0000x reference)
#include <cuda_runtime.h>

// YoloLayer2: x (16, 3*85, 76, 76) f32 -> out (16, 3, 76, 76, 85) f32
// R14 front-batched-load structure scaled to TILE_P=128 / 512 threads:
//  - all 6 float4 LDGs per thread issued back-to-back (MLP=6) before compute
//  - warp-shaped map (4 attrs x 8 quads/warp) -> conflict-free transposed STS
//  - .cs loads (dead after read), default cached stores
//  - 48 warps/SM (3 CTAs), half the barrier generations of the 64-pixel tile

#define NUM_B 16
#define NUM_A 3
#define DIM_H 76
#define DIM_W 76
#define HW (DIM_H * DIM_W)        // 5776
#define ATTR 85
#define TILE_P 128                // pixels per block (smem = 128*85*4 = 43520 B)
#define NTHREADS 512
#define NWARPS (NTHREADS / 32)    // 16
#define WITERS 88                 // 22 attr-groups (88 virtual attrs) * 4 m-quarters
#define MAXIT 6                   // ceil(WITERS / NWARPS)

// sigmoid(v) = 0.5*tanh(v/2) + 0.5  -- single MUFU (tanh.approx) + FMA
__device__ __forceinline__ float fsigmoid(float v) {
    float t;
    asm("tanh.approx.f32 %0, %1;" : "=f"(t) : "f"(v * 0.5f));
    return fmaf(t, 0.5f, 0.5f);
}

// streaming load: input is dead after one read
__device__ __forceinline__ float4 ldcs4(const float* p) {
    float4 r;
    asm("ld.global.cs.v4.f32 {%0,%1,%2,%3}, [%4];"
        : "=f"(r.x), "=f"(r.y), "=f"(r.z), "=f"(r.w) : "l"(p));
    return r;
}

__global__ __launch_bounds__(NTHREADS, 3)
void yolo_kernel(const float* __restrict__ x, float* __restrict__ out) {
    __shared__ float sm[TILE_P * ATTR];   // 43520 bytes

    const int tile = blockIdx.x;          // pixel tile within (b,a)
    const int ba   = blockIdx.y;          // b*3 + a, 0..47
    const int a    = ba % NUM_A;

    // anchor_w = masked[0:3] = {10,13,16}; anchor_h = masked[1:4] = {13,16,30}
    const float AW[3] = {10.0f, 13.0f, 16.0f};
    const float AH[3] = {13.0f, 16.0f, 30.0f};
    const float sw = AW[a] * (1.0f / 608.0f);
    const float sh = AH[a] * (1.0f / 608.0f);

    const int p0     = tile * TILE_P;
    const int nvalid = min(TILE_P, HW - p0);   // 128, or 16 on the last tile
    const int tid    = threadIdx.x;
    const int warp   = tid >> 5;
    const int lane   = tid & 31;

    const int attr_lo = lane >> 3;        // 0..3 within attr-group
    const int m_lo    = lane & 7;         // 0..7 within m-quarter

    const float* __restrict__ base_in = x + (size_t)ba * ATTR * HW + p0;

    // Item i -> wi = warp + i*NWARPS; attr = 4*(wi>>2)+attr_lo (88 virtual),
    // m = 8*(wi&3)+m_lo (0..31), pl = 4m.
    int  attr_v[MAXIT], pl_v[MAXIT];
    bool ok[MAXIT];
    #pragma unroll
    for (int i = 0; i < MAXIT; i++) {
        const int wi = warp + i * NWARPS;
        attr_v[i] = ((wi >> 2) << 2) + attr_lo;
        pl_v[i]   = (((wi & 3) << 3) + m_lo) << 2;
        ok[i] = (wi < WITERS) && (attr_v[i] < ATTR) && (pl_v[i] < nvalid);
    }

    // ---- phase 1: batch all loads (MLP = 6) ----
    float4 v[MAXIT];
    #pragma unroll
    for (int i = 0; i < MAXIT; i++)
        if (ok[i]) v[i] = ldcs4(base_in + attr_v[i] * HW + pl_v[i]);

    // ---- phase 2: compute + conflict-free transposed STS ----
    // bank = (20*m + 21*k + attr) mod 32: per k, all 32 lanes distinct.
    #pragma unroll
    for (int i = 0; i < MAXIT; i++) {
        if (!ok[i]) continue;
        const int attr = attr_v[i];
        const int pl   = pl_v[i];
        float vv[4] = {v[i].x, v[i].y, v[i].z, v[i].w};
        float r[4];

        if (attr >= 4) {
            #pragma unroll
            for (int k = 0; k < 4; k++) r[k] = fsigmoid(vv[k]);
        } else if (attr == 0) {
            #pragma unroll
            for (int k = 0; k < 4; k++) {
                const int p   = p0 + pl + k;
                const int wi2 = p % DIM_W;
                r[k] = ((float)wi2 + fsigmoid(vv[k])) * (1.0f / 76.0f);
            }
        } else if (attr == 1) {
            #pragma unroll
            for (int k = 0; k < 4; k++) {
                const int p  = p0 + pl + k;
                const int hj = p / DIM_W;
                r[k] = ((float)hj + fsigmoid(vv[k])) * (1.0f / 76.0f);
            }
        } else if (attr == 2) {
            #pragma unroll
            for (int k = 0; k < 4; k++) r[k] = __expf(vv[k]) * sw;
        } else { // attr == 3
            #pragma unroll
            for (int k = 0; k < 4; k++) r[k] = __expf(vv[k]) * sh;
        }

        float* __restrict__ row = sm + pl * ATTR + attr;
        #pragma unroll
        for (int k = 0; k < 4; k++) row[k * ATTR] = r[k];
    }
    __syncthreads();

    // Coalesced flat write of nvalid*85 contiguous floats (multiple of 4).
    // Default cache policy: L2 write caching absorbs the store burst.
    float* __restrict__ base_out = out + (size_t)(ba * HW + p0) * ATTR;
    const int total4 = (nvalid * ATTR) >> 2;
    const float4* __restrict__ s4 = (const float4*)sm;
    float4* __restrict__ o4 = (float4*)base_out;
    for (int k = tid; k < total4; k += NTHREADS) {
        o4[k] = s4[k];
    }
}

extern "C" void kernel_launch(void* const* d_in, const int* in_sizes, int n_in,
                              void* d_out, int out_size) {
    const float* x = (const float*)d_in[0];
    float* out = (float*)d_out;
    dim3 grid((HW + TILE_P - 1) / TILE_P, NUM_B * NUM_A);  // (46, 48)
    yolo_kernel<<<grid, NTHREADS>>>(x, out);
}